// round 11
// baseline (speedup 1.0000x reference)
#include <cuda_runtime.h>
#include <cuda_fp16.h>
#include <cstdint>

// Problem dims
#define BB 32
#define NN 1024
#define DD 256
#define HH 512
#define HB_ELEMS (BB * NN * DD)
#define QKV_ELEMS (BB * NN * HH)
#define S_ELEMS ((long long)BB * NN * NN)
#define W1_ELEMS (HH * DD)
#define NTILE 8

// ---------------- scratch ----------------
__device__ __half g_h16[HB_ELEMS];
__device__ __half g_wq16[W1_ELEMS], g_wk16[W1_ELEMS], g_wv16[W1_ELEMS];
__device__ __half g_wo2[2 * W1_ELEMS];
__device__ __half g_q[QKV_ELEMS], g_k[QKV_ELEMS];
__device__ __half g_vt[QKV_ELEMS];              // [b][h][n]
__device__ __half g_e[S_ELEMS];
__device__ float  g_mloc[BB * NTILE * NN];
__device__ float  g_rsum[BB * NTILE * NN];
__device__ __half g_o2[2 * QKV_ELEMS];

// ---------------- helpers ----------------
__device__ __forceinline__ void h_split(float x, __half& h, __half& l) {
    h = __float2half_rn(x);
    l = __float2half_rn(x - __half2float(h));
}
__device__ __forceinline__ uint32_t packh2(__half a, __half b) {
    __half2 t = __halves2half2(a, b);
    return *reinterpret_cast<uint32_t*>(&t);
}
__device__ __forceinline__ uint32_t mulh2(uint32_t a, __half2 s) {
    __half2 x = *reinterpret_cast<__half2*>(&a);
    x = __hmul2(x, s);
    return *reinterpret_cast<uint32_t*>(&x);
}
__device__ __forceinline__ uint32_t smem_u32(const void* p) {
    uint32_t a;
    asm("{ .reg .u64 t; cvta.to.shared.u64 t, %1; cvt.u32.u64 %0, t; }" : "=r"(a) : "l"(p));
    return a;
}
__device__ __forceinline__ void cp16(uint32_t dst, const void* src) {
    asm volatile("cp.async.cg.shared.global [%0], [%1], 16;" :: "r"(dst), "l"(src));
}
#define CP_COMMIT() asm volatile("cp.async.commit_group;" ::: "memory")
#define CP_WAIT(n)  asm volatile("cp.async.wait_group %0;" :: "n"(n) : "memory")

__device__ __forceinline__ void ldsm4(uint32_t* r, uint32_t addr) {
    asm volatile("ldmatrix.sync.aligned.m8n8.x4.shared.b16 {%0,%1,%2,%3}, [%4];"
        : "=r"(r[0]), "=r"(r[1]), "=r"(r[2]), "=r"(r[3]) : "r"(addr));
}
__device__ __forceinline__ void mma_f16(float* d, const uint32_t* a, const uint32_t* b) {
    asm volatile(
        "mma.sync.aligned.m16n8k16.row.col.f32.f16.f16.f32 "
        "{%0,%1,%2,%3}, {%4,%5,%6,%7}, {%8,%9}, {%0,%1,%2,%3};"
        : "+f"(d[0]), "+f"(d[1]), "+f"(d[2]), "+f"(d[3])
        : "r"(a[0]), "r"(a[1]), "r"(a[2]), "r"(a[3]), "r"(b[0]), "r"(b[1]));
}

// ---------------- tile config ----------------
#define BM 128
#define BN 128
#define T128 128                         // single-plane kernels: 4 warps
#define T256 256                         // pair GEMM / pack

// single-plane GEMMs: BK=64, pitch 144 B, 3 stages, 2 CTAs/SM
#define BK64 64
#define PITCH64 144
#define PLANE64 (128 * PITCH64)
#define SSTAGES 3
#define SSTAGE_B (2 * PLANE64)
#define SSMEM (SSTAGES * SSTAGE_B)       // 110592

// pair GEMM: BK=32, pitch 80 B, 3 stages
#define BK32 32
#define PLANE32 (128 * 80)
#define PSTAGES 3
#define PSTAGE_B (4 * PLANE32)
#define PSMEM (PSTAGES * PSTAGE_B)

// transposed-epilogue staging pitch (halves)
#define PT 132

// ---- mainloop load macro (BK=64 single-plane, 128 threads) ----
#define ISSUE64(Ab, Bb, Kdim, it)                                              \
    do {                                                                       \
        const int s_ = (it) % SSTAGES;                                         \
        const int k0_ = (it) * BK64;                                           \
        const uint32_t stg_ = sbase + s_ * SSTAGE_B;                           \
        _Pragma("unroll")                                                      \
        for (int c_ = 0; c_ < 16; c_++) {                                      \
            const int id_ = tid + c_ * 128;                                    \
            const int seg_ = id_ >> 10;                                        \
            const int rid_ = id_ & 1023;                                       \
            const int row_ = rid_ >> 3, ch_ = rid_ & 7;                        \
            const __half* src_ = seg_ ? (Bb + (long long)(n0 + row_) * Kdim)   \
                                      : (Ab + (long long)(m0 + row_) * Kdim);  \
            cp16(stg_ + seg_ * PLANE64 + row_ * PITCH64 + ch_ * 16,            \
                 src_ + k0_ + ch_ * 8);                                        \
        }                                                                      \
    } while (0)

// 64x64 warp tile mainloop step (shared by all single-plane kernels)
#define MAINLOOP_STEP(stg)                                                     \
    _Pragma("unroll")                                                          \
    for (int kk = 0; kk < BK64; kk += 16) {                                    \
        uint32_t Af[4][4];                                                     \
        _Pragma("unroll")                                                      \
        for (int i = 0; i < 4; i++)                                            \
            ldsm4(Af[i], (stg) + (uint32_t)(wm + i * 16 + a_row) * PITCH64     \
                       + (uint32_t)(kk + a_kc) * 2);                           \
        _Pragma("unroll")                                                      \
        for (int p = 0; p < 4; p++) {                                          \
            uint32_t Bf[4];                                                    \
            ldsm4(Bf, (stg) + PLANE64                                          \
                     + (uint32_t)(wn + p * 16 + b_n) * PITCH64                 \
                     + (uint32_t)(kk + b_kc) * 2);                             \
            _Pragma("unroll")                                                  \
            for (int i = 0; i < 4; i++) {                                      \
                mma_f16(acc[i][2 * p],     Af[i], &Bf[0]);                     \
                mma_f16(acc[i][2 * p + 1], Af[i], &Bf[2]);                     \
            }                                                                  \
        }                                                                      \
    }

#define ACC_DECL                                                               \
    float acc[4][8][4];                                                        \
    _Pragma("unroll")                                                          \
    for (int i = 0; i < 4; i++)                                                \
        _Pragma("unroll")                                                      \
        for (int j = 0; j < 8; j++)                                            \
            _Pragma("unroll")                                                  \
            for (int r = 0; r < 4; r++) acc[i][j][r] = 0.0f;

#define FRAG_IDX                                                               \
    const int a_row = lane & 15;                                               \
    const int a_kc = (lane >> 4) * 8;                                          \
    const int b_n = ((lane >> 4) << 3) + (lane & 7);                           \
    const int b_kc = ((lane >> 3) & 1) * 8;

// ===========================================================================
// Fused Q/K/V projection (4 warps, 64x64 warp tiles)
// ===========================================================================
__global__ __launch_bounds__(T128, 2) void gemm_proj(
    const __half* __restrict__ Hm,
    const __half* __restrict__ Wqp, const __half* __restrict__ Wkp,
    const __half* __restrict__ Wvp,
    const float* __restrict__ bqp, const float* __restrict__ bkp,
    const float* __restrict__ bvp,
    __half* __restrict__ Qp, __half* __restrict__ Kp, __half* __restrict__ Vtp)
{
    extern __shared__ char smc[];
    const uint32_t sbase = smem_u32(smc);

    const int tid = threadIdx.x;
    const int wid = tid >> 5;
    const int lane = tid & 31;
    const int g = lane >> 2;
    const int t = lane & 3;
    const int z = blockIdx.z;

    const __half* Ab = Hm;
    const __half* Bb = (z == 0) ? Wqp : (z == 1) ? Wkp : Wvp;
    const float* bias = (z == 0) ? bqp : (z == 1) ? bkp : bvp;

    const int m0 = blockIdx.y * BM;
    const int n0 = blockIdx.x * BN;
    const int wm = (wid & 1) * 64;
    const int wn = (wid >> 1) * 64;
    const int K = DD, N = HH;

    ACC_DECL;
    const int niter = K / BK64;     // 4

#pragma unroll
    for (int it = 0; it < SSTAGES - 1; it++) { ISSUE64(Ab, Bb, K, it); CP_COMMIT(); }

    FRAG_IDX;

    for (int it = 0; it < niter; it++) {
        CP_WAIT(SSTAGES - 2);
        __syncthreads();
        if (it + SSTAGES - 1 < niter) { ISSUE64(Ab, Bb, K, it + SSTAGES - 1); }
        CP_COMMIT();
        const uint32_t stg = sbase + (it % SSTAGES) * SSTAGE_B;
        MAINLOOP_STEP(stg);
    }

    if (z < 2) {
        __half* C = (z == 0) ? Qp : Kp;
#pragma unroll
        for (int i = 0; i < 4; i++) {
            const int r0 = m0 + wm + i * 16 + g;
#pragma unroll
            for (int j = 0; j < 8; j++) {
                const int cc = n0 + wn + j * 8 + 2 * t;
                float b0 = bias[cc], b1 = bias[cc + 1];
                float x0 = fmaxf(acc[i][j][0] + b0, 0.f);
                float x1 = fmaxf(acc[i][j][1] + b1, 0.f);
                float x2 = fmaxf(acc[i][j][2] + b0, 0.f);
                float x3 = fmaxf(acc[i][j][3] + b1, 0.f);
                *(uint32_t*)(C + (long long)r0 * N + cc) =
                    packh2(__float2half_rn(x0), __float2half_rn(x1));
                *(uint32_t*)(C + (long long)(r0 + 8) * N + cc) =
                    packh2(__float2half_rn(x2), __float2half_rn(x3));
            }
        }
    } else {
        // V: stage tile in smem, write transposed vt[b][h][n]
        __syncthreads();
        __half* tile = (__half*)smc;
#pragma unroll
        for (int i = 0; i < 4; i++) {
            const int rl0 = wm + i * 16 + g;
#pragma unroll
            for (int j = 0; j < 8; j++) {
                const int cl = wn + j * 8 + 2 * t;
                float b0 = bias[n0 + cl], b1 = bias[n0 + cl + 1];
                tile[rl0 * PT + cl]           = __float2half_rn(fmaxf(acc[i][j][0] + b0, 0.f));
                tile[rl0 * PT + cl + 1]       = __float2half_rn(fmaxf(acc[i][j][1] + b1, 0.f));
                tile[(rl0 + 8) * PT + cl]     = __float2half_rn(fmaxf(acc[i][j][2] + b0, 0.f));
                tile[(rl0 + 8) * PT + cl + 1] = __float2half_rn(fmaxf(acc[i][j][3] + b1, 0.f));
            }
        }
        __syncthreads();
        const int b = m0 >> 10;
        const int nloc = m0 & 1023;
        __half* vtb = Vtp + (long long)b * HH * NN + nloc;
#pragma unroll
        for (int jc = 0; jc < 128; jc++)
            vtb[(long long)(n0 + jc) * NN + tid] = tile[tid * PT + jc];
    }
}

// ===========================================================================
// S GEMM with online-exp epilogue (4 warps, 64x64)
// ===========================================================================
__global__ __launch_bounds__(T128, 2) void gemm_qk(
    const __half* __restrict__ Q, const __half* __restrict__ Kx,
    __half* __restrict__ E, float* __restrict__ mloc, float* __restrict__ rsum)
{
    extern __shared__ char smc[];
    __shared__ float sred[2][128];
    const uint32_t sbase = smem_u32(smc);

    const int tid = threadIdx.x;
    const int wid = tid >> 5;
    const int lane = tid & 31;
    const int g = lane >> 2;
    const int t = lane & 3;
    const int bz = blockIdx.z;

    const __half* Ab = Q + ((long long)bz * NN * HH);
    const __half* Bb = Kx + ((long long)bz * NN * HH);
    const int m0 = blockIdx.y * BM;
    const int n0 = blockIdx.x * BN;
    const int wm = (wid & 1) * 64;
    const int wn = (wid >> 1) * 64;
    const int K = HH;

    ACC_DECL;
    const int niter = K / BK64;   // 8

#pragma unroll
    for (int it = 0; it < SSTAGES - 1; it++) { ISSUE64(Ab, Bb, K, it); CP_COMMIT(); }

    FRAG_IDX;

    for (int it = 0; it < niter; it++) {
        CP_WAIT(SSTAGES - 2);
        __syncthreads();
        if (it + SSTAGES - 1 < niter) { ISSUE64(Ab, Bb, K, it + SSTAGES - 1); }
        CP_COMMIT();
        const uint32_t stg = sbase + (it % SSTAGES) * SSTAGE_B;
        MAINLOOP_STEP(stg);
    }

    // ---- online-exp epilogue ----
    int R[8];
#pragma unroll
    for (int i = 0; i < 4; i++) { R[2 * i] = wm + i * 16 + g; R[2 * i + 1] = wm + i * 16 + 8 + g; }
    const int half = wid >> 1;

    float rm[8];
#pragma unroll
    for (int k = 0; k < 8; k++) rm[k] = -1e30f;
#pragma unroll
    for (int i = 0; i < 4; i++)
#pragma unroll
        for (int j = 0; j < 8; j++) {
            rm[2 * i]     = fmaxf(rm[2 * i],     fmaxf(acc[i][j][0], acc[i][j][1]));
            rm[2 * i + 1] = fmaxf(rm[2 * i + 1], fmaxf(acc[i][j][2], acc[i][j][3]));
        }
#pragma unroll
    for (int o = 1; o <= 2; o <<= 1)
#pragma unroll
        for (int k = 0; k < 8; k++)
            rm[k] = fmaxf(rm[k], __shfl_xor_sync(0xffffffffu, rm[k], o));

    __syncthreads();
    if (t == 0) {
#pragma unroll
        for (int k = 0; k < 8; k++) sred[half][R[k]] = rm[k];
    }
    __syncthreads();
    float gm[8];
#pragma unroll
    for (int k = 0; k < 8; k++) gm[k] = fmaxf(sred[0][R[k]], sred[1][R[k]]);
    __syncthreads();

    float rs[8];
#pragma unroll
    for (int k = 0; k < 8; k++) rs[k] = 0.f;
#pragma unroll
    for (int i = 0; i < 4; i++)
#pragma unroll
        for (int j = 0; j < 8; j++) {
            acc[i][j][0] = __expf(acc[i][j][0] - gm[2 * i]);
            acc[i][j][1] = __expf(acc[i][j][1] - gm[2 * i]);
            rs[2 * i] += acc[i][j][0] + acc[i][j][1];
            acc[i][j][2] = __expf(acc[i][j][2] - gm[2 * i + 1]);
            acc[i][j][3] = __expf(acc[i][j][3] - gm[2 * i + 1]);
            rs[2 * i + 1] += acc[i][j][2] + acc[i][j][3];
        }
#pragma unroll
    for (int o = 1; o <= 2; o <<= 1)
#pragma unroll
        for (int k = 0; k < 8; k++)
            rs[k] += __shfl_xor_sync(0xffffffffu, rs[k], o);

    if (t == 0 && half == 0) {
#pragma unroll
        for (int k = 0; k < 8; k++) sred[0][R[k]] = rs[k];
    }
    __syncthreads();
    if (t == 0 && half == 1) {
#pragma unroll
        for (int k = 0; k < 8; k++) atomicAdd(&sred[0][R[k]], rs[k]);
    }
    __syncthreads();

    if (t == 0 && half == 0) {
        const long long sb = ((long long)(bz * NTILE + blockIdx.x) << 10) + m0;
#pragma unroll
        for (int k = 0; k < 8; k++) {
            mloc[sb + R[k]] = gm[k];
            rsum[sb + R[k]] = sred[0][R[k]];
        }
    }

    __half* Eb = E + ((long long)bz << 20);
#pragma unroll
    for (int i = 0; i < 4; i++) {
        const int r0 = m0 + wm + i * 16 + g;
#pragma unroll
        for (int j = 0; j < 8; j++) {
            const int cc = n0 + wn + j * 8 + 2 * t;
            *(uint32_t*)(Eb + (long long)r0 * NN + cc) =
                packh2(__float2half_rn(acc[i][j][0]), __float2half_rn(acc[i][j][1]));
            *(uint32_t*)(Eb + (long long)(r0 + 8) * NN + cc) =
                packh2(__float2half_rn(acc[i][j][2]), __float2half_rn(acc[i][j][3]));
        }
    }
}

// ===========================================================================
// O GEMM: O = (diag-scaled E) * Vt^T -> half-pair, stats inlined (4 warps)
// ===========================================================================
__global__ __launch_bounds__(T128, 2) void gemm_pv(
    const __half* __restrict__ E, const __half* __restrict__ Vt,
    const float* __restrict__ mloc, const float* __restrict__ rsum,
    __half* __restrict__ O2, long long sPC)
{
    extern __shared__ char smc[];
    __shared__ float sscl[NTILE][128];
    const uint32_t sbase = smem_u32(smc);

    const int tid = threadIdx.x;
    const int wid = tid >> 5;
    const int lane = tid & 31;
    const int g = lane >> 2;
    const int t = lane & 3;
    const int bz = blockIdx.z;

    const __half* Ab = E + ((long long)bz << 20);
    const __half* Bb = Vt + ((long long)bz * HH * NN);
    const int m0 = blockIdx.y * BM;
    const int n0 = blockIdx.x * BN;
    const int wm = (wid & 1) * 64;
    const int wn = (wid >> 1) * 64;
    const int N = HH, K = NN;

    // inline stats: 128 rows by 128 threads (identical op order to R9)
    {
        const int r = m0 + tid;
        float m[NTILE], s[NTILE];
        float M = -1e30f;
#pragma unroll
        for (int tt = 0; tt < NTILE; tt++) {
            const long long p = ((long long)(bz * NTILE + tt) << 10) + r;
            m[tt] = mloc[p]; s[tt] = rsum[p];
            M = fmaxf(M, m[tt]);
        }
        float denom = 0.f;
#pragma unroll
        for (int tt = 0; tt < NTILE; tt++) {
            m[tt] = __expf(m[tt] - M);
            denom += s[tt] * m[tt];
        }
        const float inv = 1.0f / denom;
#pragma unroll
        for (int tt = 0; tt < NTILE; tt++)
            sscl[tt][tid] = m[tt] * inv;
    }

    ACC_DECL;
    const int niter = K / BK64;   // 16

#pragma unroll
    for (int it = 0; it < SSTAGES - 1; it++) { ISSUE64(Ab, Bb, K, it); CP_COMMIT(); }
    __syncthreads();   // sscl ready

    FRAG_IDX;

    int R[8];
#pragma unroll
    for (int i = 0; i < 4; i++) { R[2 * i] = wm + i * 16 + g; R[2 * i + 1] = wm + i * 16 + 8 + g; }
    __half2 hs[8];

    for (int it = 0; it < niter; it++) {
        CP_WAIT(SSTAGES - 2);
        __syncthreads();
        if (it + SSTAGES - 1 < niter) { ISSUE64(Ab, Bb, K, it + SSTAGES - 1); }
        CP_COMMIT();

        if ((it & 1) == 0) {
            const int tt = it >> 1;
#pragma unroll
            for (int k = 0; k < 8; k++) hs[k] = __float2half2_rn(sscl[tt][R[k]]);
        }

        const uint32_t stg = sbase + (it % SSTAGES) * SSTAGE_B;
#pragma unroll
        for (int kk = 0; kk < BK64; kk += 16) {
            uint32_t Af[4][4];
#pragma unroll
            for (int i = 0; i < 4; i++) {
                ldsm4(Af[i], stg + (uint32_t)(wm + i * 16 + a_row) * PITCH64
                           + (uint32_t)(kk + a_kc) * 2);
                Af[i][0] = mulh2(Af[i][0], hs[2 * i]);
                Af[i][1] = mulh2(Af[i][1], hs[2 * i + 1]);
                Af[i][2] = mulh2(Af[i][2], hs[2 * i]);
                Af[i][3] = mulh2(Af[i][3], hs[2 * i + 1]);
            }
#pragma unroll
            for (int p = 0; p < 4; p++) {
                uint32_t Bf[4];
                ldsm4(Bf, stg + PLANE64 + (uint32_t)(wn + p * 16 + b_n) * PITCH64
                                        + (uint32_t)(kk + b_kc) * 2);
#pragma unroll
                for (int i = 0; i < 4; i++) {
                    mma_f16(acc[i][2 * p],     Af[i], &Bf[0]);
                    mma_f16(acc[i][2 * p + 1], Af[i], &Bf[2]);
                }
            }
        }
    }

    __half* Ch = O2 + (long long)bz * NN * HH;
    __half* Cl = Ch + sPC;
#pragma unroll
    for (int i = 0; i < 4; i++) {
        const int r0 = m0 + wm + i * 16 + g;
#pragma unroll
        for (int j = 0; j < 8; j++) {
            const int cc = n0 + wn + j * 8 + 2 * t;
            __half h0, l0, h1, l1, h2, l2, h3, l3;
            h_split(acc[i][j][0], h0, l0); h_split(acc[i][j][1], h1, l1);
            h_split(acc[i][j][2], h2, l2); h_split(acc[i][j][3], h3, l3);
            *(uint32_t*)(Ch + (long long)r0 * N + cc)       = packh2(h0, h1);
            *(uint32_t*)(Cl + (long long)r0 * N + cc)       = packh2(l0, l1);
            *(uint32_t*)(Ch + (long long)(r0 + 8) * N + cc) = packh2(h2, h3);
            *(uint32_t*)(Cl + (long long)(r0 + 8) * N + cc) = packh2(l2, l3);
        }
    }
}

// ===========================================================================
// Pair fp16 NT GEMM (3 MMAs), 256 threads — UNCHANGED
// ===========================================================================
__global__ __launch_bounds__(T256) void gemm_p3(
    const __half* __restrict__ A, const __half* __restrict__ B,
    const float* __restrict__ bias, float* __restrict__ C,
    int M, int N, int K, long long sPA, long long sPB)
{
    extern __shared__ char smc[];
    const uint32_t sbase = smem_u32(smc);

    const int tid = threadIdx.x;
    const int wid = tid >> 5;
    const int lane = tid & 31;
    const int g = lane >> 2;
    const int t = lane & 3;

    const __half* Ah = A;
    const __half* Al = A + sPA;
    const __half* Bh = B;
    const __half* Bl = B + sPB;
    const int m0 = blockIdx.y * BM;
    const int n0 = blockIdx.x * BN;
    const int wm = (wid & 3) * 32;
    const int wn = (wid >> 2) * 64;

    float acc[2][8][4];
#pragma unroll
    for (int i = 0; i < 2; i++)
#pragma unroll
        for (int j = 0; j < 8; j++)
#pragma unroll
            for (int r = 0; r < 4; r++) acc[i][j][r] = 0.0f;

    const int niter = K / BK32;

    auto issue_loads = [&](int it) {
        const int s = it % PSTAGES;
        const int k0 = it * BK32;
        const uint32_t stg = sbase + s * PSTAGE_B;
#pragma unroll
        for (int c = 0; c < 8; c++) {
            const int id = tid + c * 256;
            const int seg = id >> 9;
            const int rid = id & 511;
            const int row = rid >> 2, ch = rid & 3;
            const __half* src;
            int grow;
            if (seg < 2) { src = (seg == 0) ? Ah : Al; grow = m0 + row; }
            else         { src = (seg == 2) ? Bh : Bl; grow = n0 + row; }
            cp16(stg + seg * PLANE32 + row * 80 + ch * 16,
                 src + (long long)grow * K + k0 + ch * 8);
        }
    };

#pragma unroll
    for (int it = 0; it < PSTAGES - 1; it++) { issue_loads(it); CP_COMMIT(); }

    const int a_row = lane & 15;
    const int a_kc = (lane >> 4) * 8;
    const int b_n = ((lane >> 4) << 3) + (lane & 7);
    const int b_kc = ((lane >> 3) & 1) * 8;

    for (int it = 0; it < niter; it++) {
        CP_WAIT(PSTAGES - 2);
        __syncthreads();
        if (it + PSTAGES - 1 < niter) issue_loads(it + PSTAGES - 1);
        CP_COMMIT();

        const uint32_t stg = sbase + (it % PSTAGES) * PSTAGE_B;
#pragma unroll
        for (int kk = 0; kk < BK32; kk += 16) {
            uint32_t Afh[2][4], Afl[2][4];
#pragma unroll
            for (int i = 0; i < 2; i++) {
                const uint32_t ao = (uint32_t)(wm + i * 16 + a_row) * 80
                                  + (uint32_t)(kk + a_kc) * 2;
                ldsm4(Afh[i], stg + ao);
                ldsm4(Afl[i], stg + PLANE32 + ao);
            }
#pragma unroll
            for (int p = 0; p < 4; p++) {
                uint32_t Bfh[4], Bfl[4];
                const uint32_t bo = (uint32_t)(wn + p * 16 + b_n) * 80
                                  + (uint32_t)(kk + b_kc) * 2;
                ldsm4(Bfh, stg + 2 * PLANE32 + bo);
                ldsm4(Bfl, stg + 3 * PLANE32 + bo);
#pragma unroll
                for (int i = 0; i < 2; i++) {
                    mma_f16(acc[i][2 * p],     Afh[i], &Bfh[0]);
                    mma_f16(acc[i][2 * p],     Afl[i], &Bfh[0]);
                    mma_f16(acc[i][2 * p],     Afh[i], &Bfl[0]);
                    mma_f16(acc[i][2 * p + 1], Afh[i], &Bfh[2]);
                    mma_f16(acc[i][2 * p + 1], Afl[i], &Bfh[2]);
                    mma_f16(acc[i][2 * p + 1], Afh[i], &Bfl[2]);
                }
            }
        }
    }

#pragma unroll
    for (int i = 0; i < 2; i++) {
        const int r0 = m0 + wm + i * 16 + g;
#pragma unroll
        for (int j = 0; j < 8; j++) {
            const int cc = n0 + wn + j * 8 + 2 * t;
            float b0 = bias[cc], b1 = bias[cc + 1];
            *(float2*)(C + (long long)r0 * N + cc) =
                make_float2(fmaxf(acc[i][j][0] + b0, 0.f), fmaxf(acc[i][j][1] + b1, 0.f));
            *(float2*)(C + (long long)(r0 + 8) * N + cc) =
                make_float2(fmaxf(acc[i][j][2] + b0, 0.f), fmaxf(acc[i][j][3] + b1, 0.f));
        }
    }
}

// ---------------------------------------------------------------------------
// fused pack (unchanged)
// ---------------------------------------------------------------------------
#define PK_H (HB_ELEMS / 4)
#define PK_W (W1_ELEMS / 4)
__global__ __launch_bounds__(256) void pack_all(
    const float* __restrict__ h, const float* __restrict__ Wq,
    const float* __restrict__ Wk, const float* __restrict__ Wv,
    const float* __restrict__ Wo,
    __half* __restrict__ h16, __half* __restrict__ wq16,
    __half* __restrict__ wk16, __half* __restrict__ wv16,
    __half* __restrict__ wo2)
{
    const int total = PK_H + 4 * PK_W;
    for (int i = blockIdx.x * blockDim.x + threadIdx.x; i < total;
         i += gridDim.x * blockDim.x) {
        if (i < PK_H + 3 * PK_W) {
            const float* src; __half* dst; int idx;
            if (i < PK_H) { src = h; dst = h16; idx = i; }
            else {
                int r = i - PK_H;
                int seg = r / PK_W; idx = r % PK_W;
                src = (seg == 0) ? Wq : (seg == 1) ? Wk : Wv;
                dst = (seg == 0) ? wq16 : (seg == 1) ? wk16 : wv16;
            }
            float4 v = ((const float4*)src)[idx];
            ((uint2*)dst)[idx] = make_uint2(
                packh2(__float2half_rn(v.x), __float2half_rn(v.y)),
                packh2(__float2half_rn(v.z), __float2half_rn(v.w)));
        } else {
            int idx = i - PK_H - 3 * PK_W;
            float4 v = ((const float4*)Wo)[idx];
            __half h0, l0, h1, l1, h2, l2, h3, l3;
            h_split(v.x, h0, l0); h_split(v.y, h1, l1);
            h_split(v.z, h2, l2); h_split(v.w, h3, l3);
            ((uint2*)wo2)[idx] = make_uint2(packh2(h0, h1), packh2(h2, h3));
            ((uint2*)(wo2 + 2 * W1_ELEMS))[idx] = make_uint2(packh2(l0, l1), packh2(l2, l3));
        }
    }
}

// ---------------------------------------------------------------------------
// kernel_launch — inputs: h, Wv, bv, Wk, bk, Wq, bq, Wo, bo
// ---------------------------------------------------------------------------
extern "C" void kernel_launch(void* const* d_in, const int* in_sizes, int n_in,
                              void* d_out, int out_size)
{
    const float* h  = (const float*)d_in[0];
    const float* Wv = (const float*)d_in[1];
    const float* bv = (const float*)d_in[2];
    const float* Wk = (const float*)d_in[3];
    const float* bk = (const float*)d_in[4];
    const float* Wq = (const float*)d_in[5];
    const float* bq = (const float*)d_in[6];
    const float* Wo = (const float*)d_in[7];
    const float* bo = (const float*)d_in[8];
    float* out = (float*)d_out;

    __half *h16, *wq16, *wk16, *wv16, *wo2, *q, *k, *vt, *e, *o2;
    float *mloc, *rsum;
    cudaGetSymbolAddress((void**)&h16,  g_h16);
    cudaGetSymbolAddress((void**)&wq16, g_wq16);
    cudaGetSymbolAddress((void**)&wk16, g_wk16);
    cudaGetSymbolAddress((void**)&wv16, g_wv16);
    cudaGetSymbolAddress((void**)&wo2,  g_wo2);
    cudaGetSymbolAddress((void**)&q,    g_q);
    cudaGetSymbolAddress((void**)&k,    g_k);
    cudaGetSymbolAddress((void**)&vt,   g_vt);
    cudaGetSymbolAddress((void**)&e,    g_e);
    cudaGetSymbolAddress((void**)&mloc, g_mloc);
    cudaGetSymbolAddress((void**)&rsum, g_rsum);
    cudaGetSymbolAddress((void**)&o2,   g_o2);

    cudaFuncSetAttribute(gemm_proj, cudaFuncAttributeMaxDynamicSharedMemorySize, SSMEM);
    cudaFuncSetAttribute(gemm_qk,   cudaFuncAttributeMaxDynamicSharedMemorySize, SSMEM);
    cudaFuncSetAttribute(gemm_pv,   cudaFuncAttributeMaxDynamicSharedMemorySize, SSMEM);
    cudaFuncSetAttribute(gemm_p3,   cudaFuncAttributeMaxDynamicSharedMemorySize, PSMEM);

    const int M = BB * NN;   // 32768

    // 1. fused pack
    pack_all<<<2048, 256>>>(h, Wq, Wk, Wv, Wo, h16, wq16, wk16, wv16, wo2);

    // 2. fused Q/K/V projections; z==2 writes vt directly
    {
        dim3 grid(HH / BN, M / BM, 3);
        gemm_proj<<<grid, T128, SSMEM>>>(h16, wq16, wk16, wv16,
                                         bq, bk, bv, q, k, vt);
    }

    // 3. S GEMM + online exp -> e fp16 + per-tile stats
    {
        dim3 grid(NN / BN, NN / BM, BB);
        gemm_qk<<<grid, T128, SSMEM>>>(q, k, e, mloc, rsum);
    }

    // 4. O = scaled-E * Vt^T -> fp16 pair (stats inlined)
    {
        dim3 grid(HH / BN, NN / BM, BB);
        gemm_pv<<<grid, T128, SSMEM>>>(e, vt, mloc, rsum, o2, QKV_ELEMS);
    }

    // 5. out = relu(O Wo^T + bo) -> fp32
    {
        dim3 grid(DD / BN, M / BM, 1);
        gemm_p3<<<grid, T256, PSMEM>>>(o2, wo2, bo, out, M, DD, HH,
                                       QKV_ELEMS, W1_ELEMS);
    }
}

// round 12
// speedup vs baseline: 1.0394x; 1.0394x over previous
#include <cuda_runtime.h>
#include <cuda_fp16.h>
#include <cstdint>

// Problem dims
#define BB 32
#define NN 1024
#define DD 256
#define HH 512
#define HB_ELEMS (BB * NN * DD)
#define QKV_ELEMS (BB * NN * HH)
#define S_ELEMS ((long long)BB * NN * NN)
#define W1_ELEMS (HH * DD)
#define NTILE 8

// ---------------- scratch ----------------
__device__ __half g_h16[HB_ELEMS];
__device__ __half g_wq16[W1_ELEMS], g_wk16[W1_ELEMS], g_wv16[W1_ELEMS];
__device__ __half g_wo2[2 * W1_ELEMS];
__device__ __half g_q[QKV_ELEMS], g_k[QKV_ELEMS];
__device__ __half g_vt[QKV_ELEMS];              // [b][h][n]
__device__ __half g_e[S_ELEMS];
__device__ float  g_mloc[BB * NTILE * NN];
__device__ float  g_rsum[BB * NTILE * NN];
__device__ __half g_o2[2 * QKV_ELEMS];

// ---------------- helpers ----------------
__device__ __forceinline__ void h_split(float x, __half& h, __half& l) {
    h = __float2half_rn(x);
    l = __float2half_rn(x - __half2float(h));
}
__device__ __forceinline__ uint32_t packh2(__half a, __half b) {
    __half2 t = __halves2half2(a, b);
    return *reinterpret_cast<uint32_t*>(&t);
}
__device__ __forceinline__ uint32_t mulh2(uint32_t a, __half2 s) {
    __half2 x = *reinterpret_cast<__half2*>(&a);
    x = __hmul2(x, s);
    return *reinterpret_cast<uint32_t*>(&x);
}
__device__ __forceinline__ uint32_t smem_u32(const void* p) {
    uint32_t a;
    asm("{ .reg .u64 t; cvta.to.shared.u64 t, %1; cvt.u32.u64 %0, t; }" : "=r"(a) : "l"(p));
    return a;
}
__device__ __forceinline__ void cp16(uint32_t dst, const void* src) {
    asm volatile("cp.async.cg.shared.global [%0], [%1], 16;" :: "r"(dst), "l"(src));
}
#define CP_COMMIT() asm volatile("cp.async.commit_group;" ::: "memory")
#define CP_WAIT(n)  asm volatile("cp.async.wait_group %0;" :: "n"(n) : "memory")

__device__ __forceinline__ void ldsm4(uint32_t* r, uint32_t addr) {
    asm volatile("ldmatrix.sync.aligned.m8n8.x4.shared.b16 {%0,%1,%2,%3}, [%4];"
        : "=r"(r[0]), "=r"(r[1]), "=r"(r[2]), "=r"(r[3]) : "r"(addr));
}
__device__ __forceinline__ void mma_f16(float* d, const uint32_t* a, const uint32_t* b) {
    asm volatile(
        "mma.sync.aligned.m16n8k16.row.col.f32.f16.f16.f32 "
        "{%0,%1,%2,%3}, {%4,%5,%6,%7}, {%8,%9}, {%0,%1,%2,%3};"
        : "+f"(d[0]), "+f"(d[1]), "+f"(d[2]), "+f"(d[3])
        : "r"(a[0]), "r"(a[1]), "r"(a[2]), "r"(a[3]), "r"(b[0]), "r"(b[1]));
}

// ---------------- tile config ----------------
#define BM 128
#define BN 128
#define THREADS 256

// single-plane GEMMs: BK=64, pitch 144 B, 3 stages, 2 CTAs/SM (R9 config)
#define BK64 64
#define PITCH64 144
#define PLANE64 (128 * PITCH64)          // 18432 B
#define SSTAGES 3
#define SSTAGE_B (2 * PLANE64)           // 36864
#define SSMEM (SSTAGES * SSTAGE_B)       // 110592

// pair GEMM (out-proj): BK=64, pitch 144 B, 2 stages, 1 CTA/SM
#define PSTAGES 2
#define PSTAGE_B (4 * PLANE64)           // 73728
#define PSMEM (PSTAGES * PSTAGE_B)       // 147456

// transposed-epilogue staging pitch (halves)
#define PT 132

// ---- mainloop load macro (BK=64 single-plane, 256 threads) ----
#define ISSUE64(Ab, Bb, Kdim, it)                                              \
    do {                                                                       \
        const int s_ = (it) % SSTAGES;                                         \
        const int k0_ = (it) * BK64;                                           \
        const uint32_t stg_ = sbase + s_ * SSTAGE_B;                           \
        _Pragma("unroll")                                                      \
        for (int c_ = 0; c_ < 8; c_++) {                                       \
            const int id_ = tid + c_ * 256;                                    \
            const int seg_ = id_ >> 10;                                        \
            const int rid_ = id_ & 1023;                                       \
            const int row_ = rid_ >> 3, ch_ = rid_ & 7;                        \
            const __half* src_ = seg_ ? (Bb + (long long)(n0 + row_) * Kdim)   \
                                      : (Ab + (long long)(m0 + row_) * Kdim);  \
            cp16(stg_ + seg_ * PLANE64 + row_ * PITCH64 + ch_ * 16,            \
                 src_ + k0_ + ch_ * 8);                                        \
        }                                                                      \
    } while (0)

// ===========================================================================
// Fused Q/K/V projection (8 warps, 32x64 warp tiles) — R9 config
// ===========================================================================
__global__ __launch_bounds__(THREADS, 2) void gemm_proj(
    const __half* __restrict__ Hm,
    const __half* __restrict__ Wqp, const __half* __restrict__ Wkp,
    const __half* __restrict__ Wvp,
    const float* __restrict__ bqp, const float* __restrict__ bkp,
    const float* __restrict__ bvp,
    __half* __restrict__ Qp, __half* __restrict__ Kp, __half* __restrict__ Vtp)
{
    extern __shared__ char smc[];
    const uint32_t sbase = smem_u32(smc);

    const int tid = threadIdx.x;
    const int wid = tid >> 5;
    const int lane = tid & 31;
    const int g = lane >> 2;
    const int t = lane & 3;
    const int z = blockIdx.z;

    const __half* Ab = Hm;
    const __half* Bb = (z == 0) ? Wqp : (z == 1) ? Wkp : Wvp;
    const float* bias = (z == 0) ? bqp : (z == 1) ? bkp : bvp;

    const int m0 = blockIdx.y * BM;
    const int n0 = blockIdx.x * BN;
    const int wm = (wid & 3) * 32;
    const int wn = (wid >> 2) * 64;
    const int K = DD, N = HH;

    float acc[2][8][4];
#pragma unroll
    for (int i = 0; i < 2; i++)
#pragma unroll
        for (int j = 0; j < 8; j++)
#pragma unroll
            for (int r = 0; r < 4; r++) acc[i][j][r] = 0.0f;

    const int niter = K / BK64;     // 4

#pragma unroll
    for (int it = 0; it < SSTAGES - 1; it++) { ISSUE64(Ab, Bb, K, it); CP_COMMIT(); }

    const int a_row = lane & 15;
    const int a_kc = (lane >> 4) * 8;
    const int b_n = ((lane >> 4) << 3) + (lane & 7);
    const int b_kc = ((lane >> 3) & 1) * 8;

    for (int it = 0; it < niter; it++) {
        CP_WAIT(SSTAGES - 2);
        __syncthreads();
        if (it + SSTAGES - 1 < niter) { ISSUE64(Ab, Bb, K, it + SSTAGES - 1); }
        CP_COMMIT();

        const uint32_t stg = sbase + (it % SSTAGES) * SSTAGE_B;
#pragma unroll
        for (int kk = 0; kk < BK64; kk += 16) {
            uint32_t Af[2][4];
#pragma unroll
            for (int i = 0; i < 2; i++)
                ldsm4(Af[i], stg + (uint32_t)(wm + i * 16 + a_row) * PITCH64
                               + (uint32_t)(kk + a_kc) * 2);
#pragma unroll
            for (int p = 0; p < 4; p++) {
                uint32_t Bf[4];
                ldsm4(Bf, stg + PLANE64 + (uint32_t)(wn + p * 16 + b_n) * PITCH64
                                        + (uint32_t)(kk + b_kc) * 2);
#pragma unroll
                for (int i = 0; i < 2; i++) {
                    mma_f16(acc[i][2 * p],     Af[i], &Bf[0]);
                    mma_f16(acc[i][2 * p + 1], Af[i], &Bf[2]);
                }
            }
        }
    }

    if (z < 2) {
        __half* C = (z == 0) ? Qp : Kp;
#pragma unroll
        for (int i = 0; i < 2; i++) {
            const int r0 = m0 + wm + i * 16 + g;
#pragma unroll
            for (int j = 0; j < 8; j++) {
                const int cc = n0 + wn + j * 8 + 2 * t;
                float b0 = bias[cc], b1 = bias[cc + 1];
                float x0 = fmaxf(acc[i][j][0] + b0, 0.f);
                float x1 = fmaxf(acc[i][j][1] + b1, 0.f);
                float x2 = fmaxf(acc[i][j][2] + b0, 0.f);
                float x3 = fmaxf(acc[i][j][3] + b1, 0.f);
                *(uint32_t*)(C + (long long)r0 * N + cc) =
                    packh2(__float2half_rn(x0), __float2half_rn(x1));
                *(uint32_t*)(C + (long long)(r0 + 8) * N + cc) =
                    packh2(__float2half_rn(x2), __float2half_rn(x3));
            }
        }
    } else {
        // V: stage tile in smem, write transposed vt[b][h][n]
        __syncthreads();
        __half* tile = (__half*)smc;
#pragma unroll
        for (int i = 0; i < 2; i++) {
            const int rl0 = wm + i * 16 + g;
#pragma unroll
            for (int j = 0; j < 8; j++) {
                const int cl = wn + j * 8 + 2 * t;
                float b0 = bias[n0 + cl], b1 = bias[n0 + cl + 1];
                tile[rl0 * PT + cl]           = __float2half_rn(fmaxf(acc[i][j][0] + b0, 0.f));
                tile[rl0 * PT + cl + 1]       = __float2half_rn(fmaxf(acc[i][j][1] + b1, 0.f));
                tile[(rl0 + 8) * PT + cl]     = __float2half_rn(fmaxf(acc[i][j][2] + b0, 0.f));
                tile[(rl0 + 8) * PT + cl + 1] = __float2half_rn(fmaxf(acc[i][j][3] + b1, 0.f));
            }
        }
        __syncthreads();
        const int b = m0 >> 10;
        const int nloc = m0 & 1023;
        __half* vtb = Vtp + (long long)b * HH * NN + nloc;
        const int g2 = tid >> 7;
        const int l128 = tid & 127;
#pragma unroll
        for (int jc = 0; jc < 64; jc++) {
            const int c = g2 * 64 + jc;
            vtb[(long long)(n0 + c) * NN + l128] = tile[l128 * PT + c];
        }
    }
}

// ===========================================================================
// S GEMM with online-exp epilogue (8 warps, 32x64) — R9 config
// ===========================================================================
__global__ __launch_bounds__(THREADS, 2) void gemm_qk(
    const __half* __restrict__ Q, const __half* __restrict__ Kx,
    __half* __restrict__ E, float* __restrict__ mloc, float* __restrict__ rsum)
{
    extern __shared__ char smc[];
    __shared__ float sred[2][128];
    const uint32_t sbase = smem_u32(smc);

    const int tid = threadIdx.x;
    const int wid = tid >> 5;
    const int lane = tid & 31;
    const int g = lane >> 2;
    const int t = lane & 3;
    const int bz = blockIdx.z;

    const __half* Ab = Q + ((long long)bz * NN * HH);
    const __half* Bb = Kx + ((long long)bz * NN * HH);
    const int m0 = blockIdx.y * BM;
    const int n0 = blockIdx.x * BN;
    const int wm = (wid & 3) * 32;
    const int wn = (wid >> 2) * 64;
    const int K = HH;

    float acc[2][8][4];
#pragma unroll
    for (int i = 0; i < 2; i++)
#pragma unroll
        for (int j = 0; j < 8; j++)
#pragma unroll
            for (int r = 0; r < 4; r++) acc[i][j][r] = 0.0f;

    const int niter = K / BK64;   // 8

#pragma unroll
    for (int it = 0; it < SSTAGES - 1; it++) { ISSUE64(Ab, Bb, K, it); CP_COMMIT(); }

    const int a_row = lane & 15;
    const int a_kc = (lane >> 4) * 8;
    const int b_n = ((lane >> 4) << 3) + (lane & 7);
    const int b_kc = ((lane >> 3) & 1) * 8;

    for (int it = 0; it < niter; it++) {
        CP_WAIT(SSTAGES - 2);
        __syncthreads();
        if (it + SSTAGES - 1 < niter) { ISSUE64(Ab, Bb, K, it + SSTAGES - 1); }
        CP_COMMIT();

        const uint32_t stg = sbase + (it % SSTAGES) * SSTAGE_B;
#pragma unroll
        for (int kk = 0; kk < BK64; kk += 16) {
            uint32_t Af[2][4];
#pragma unroll
            for (int i = 0; i < 2; i++)
                ldsm4(Af[i], stg + (uint32_t)(wm + i * 16 + a_row) * PITCH64
                               + (uint32_t)(kk + a_kc) * 2);
#pragma unroll
            for (int p = 0; p < 4; p++) {
                uint32_t Bf[4];
                ldsm4(Bf, stg + PLANE64 + (uint32_t)(wn + p * 16 + b_n) * PITCH64
                                        + (uint32_t)(kk + b_kc) * 2);
#pragma unroll
                for (int i = 0; i < 2; i++) {
                    mma_f16(acc[i][2 * p],     Af[i], &Bf[0]);
                    mma_f16(acc[i][2 * p + 1], Af[i], &Bf[2]);
                }
            }
        }
    }

    // ---- online-exp epilogue (R9 order, bit-exact) ----
    const int R0 = wm + g, R1 = wm + g + 8, R2 = wm + 16 + g, R3 = wm + 24 + g;
    const int half = wid >> 2;

    float rm[4] = {-1e30f, -1e30f, -1e30f, -1e30f};
#pragma unroll
    for (int j = 0; j < 8; j++) {
        rm[0] = fmaxf(rm[0], fmaxf(acc[0][j][0], acc[0][j][1]));
        rm[1] = fmaxf(rm[1], fmaxf(acc[0][j][2], acc[0][j][3]));
        rm[2] = fmaxf(rm[2], fmaxf(acc[1][j][0], acc[1][j][1]));
        rm[3] = fmaxf(rm[3], fmaxf(acc[1][j][2], acc[1][j][3]));
    }
#pragma unroll
    for (int o = 1; o <= 2; o <<= 1)
#pragma unroll
        for (int k = 0; k < 4; k++)
            rm[k] = fmaxf(rm[k], __shfl_xor_sync(0xffffffffu, rm[k], o));

    __syncthreads();
    if (t == 0) {
        sred[half][R0] = rm[0]; sred[half][R1] = rm[1];
        sred[half][R2] = rm[2]; sred[half][R3] = rm[3];
    }
    __syncthreads();
    float gm[4];
    gm[0] = fmaxf(sred[0][R0], sred[1][R0]);
    gm[1] = fmaxf(sred[0][R1], sred[1][R1]);
    gm[2] = fmaxf(sred[0][R2], sred[1][R2]);
    gm[3] = fmaxf(sred[0][R3], sred[1][R3]);
    __syncthreads();

    float rs[4] = {0.f, 0.f, 0.f, 0.f};
#pragma unroll
    for (int j = 0; j < 8; j++) {
        acc[0][j][0] = __expf(acc[0][j][0] - gm[0]);
        acc[0][j][1] = __expf(acc[0][j][1] - gm[0]);
        rs[0] += acc[0][j][0] + acc[0][j][1];
        acc[0][j][2] = __expf(acc[0][j][2] - gm[1]);
        acc[0][j][3] = __expf(acc[0][j][3] - gm[1]);
        rs[1] += acc[0][j][2] + acc[0][j][3];
        acc[1][j][0] = __expf(acc[1][j][0] - gm[2]);
        acc[1][j][1] = __expf(acc[1][j][1] - gm[2]);
        rs[2] += acc[1][j][0] + acc[1][j][1];
        acc[1][j][2] = __expf(acc[1][j][2] - gm[3]);
        acc[1][j][3] = __expf(acc[1][j][3] - gm[3]);
        rs[3] += acc[1][j][2] + acc[1][j][3];
    }
#pragma unroll
    for (int o = 1; o <= 2; o <<= 1)
#pragma unroll
        for (int k = 0; k < 4; k++)
            rs[k] += __shfl_xor_sync(0xffffffffu, rs[k], o);

    if (t == 0 && half == 0) {
        sred[0][R0] = rs[0]; sred[0][R1] = rs[1];
        sred[0][R2] = rs[2]; sred[0][R3] = rs[3];
    }
    __syncthreads();
    if (t == 0 && half == 1) {
        atomicAdd(&sred[0][R0], rs[0]); atomicAdd(&sred[0][R1], rs[1]);
        atomicAdd(&sred[0][R2], rs[2]); atomicAdd(&sred[0][R3], rs[3]);
    }
    __syncthreads();

    if (t == 0 && half == 0) {
        const long long sb = ((long long)(bz * NTILE + blockIdx.x) << 10) + m0;
        mloc[sb + R0] = gm[0]; rsum[sb + R0] = sred[0][R0];
        mloc[sb + R1] = gm[1]; rsum[sb + R1] = sred[0][R1];
        mloc[sb + R2] = gm[2]; rsum[sb + R2] = sred[0][R2];
        mloc[sb + R3] = gm[3]; rsum[sb + R3] = sred[0][R3];
    }

    __half* Eb = E + ((long long)bz << 20);
#pragma unroll
    for (int i = 0; i < 2; i++) {
        const int r0 = m0 + wm + i * 16 + g;
#pragma unroll
        for (int j = 0; j < 8; j++) {
            const int cc = n0 + wn + j * 8 + 2 * t;
            *(uint32_t*)(Eb + (long long)r0 * NN + cc) =
                packh2(__float2half_rn(acc[i][j][0]), __float2half_rn(acc[i][j][1]));
            *(uint32_t*)(Eb + (long long)(r0 + 8) * NN + cc) =
                packh2(__float2half_rn(acc[i][j][2]), __float2half_rn(acc[i][j][3]));
        }
    }
}

// ===========================================================================
// O GEMM: O = (diag-scaled E) * Vt^T -> half-pair, stats inlined — R9 config
// ===========================================================================
__global__ __launch_bounds__(THREADS, 2) void gemm_pv(
    const __half* __restrict__ E, const __half* __restrict__ Vt,
    const float* __restrict__ mloc, const float* __restrict__ rsum,
    __half* __restrict__ O2, long long sPC)
{
    extern __shared__ char smc[];
    __shared__ float sscl[NTILE][128];
    const uint32_t sbase = smem_u32(smc);

    const int tid = threadIdx.x;
    const int wid = tid >> 5;
    const int lane = tid & 31;
    const int g = lane >> 2;
    const int t = lane & 3;
    const int bz = blockIdx.z;

    const __half* Ab = E + ((long long)bz << 20);
    const __half* Bb = Vt + ((long long)bz * HH * NN);
    const int m0 = blockIdx.y * BM;
    const int n0 = blockIdx.x * BN;
    const int wm = (wid & 3) * 32;
    const int wn = (wid >> 2) * 64;
    const int N = HH, K = NN;

    // inline stats: 128 rows handled by threads 0..127 (identical op order)
    if (tid < 128) {
        const int r = m0 + tid;
        float m[NTILE], s[NTILE];
        float M = -1e30f;
#pragma unroll
        for (int tt = 0; tt < NTILE; tt++) {
            const long long p = ((long long)(bz * NTILE + tt) << 10) + r;
            m[tt] = mloc[p]; s[tt] = rsum[p];
            M = fmaxf(M, m[tt]);
        }
        float denom = 0.f;
#pragma unroll
        for (int tt = 0; tt < NTILE; tt++) {
            m[tt] = __expf(m[tt] - M);
            denom += s[tt] * m[tt];
        }
        const float inv = 1.0f / denom;
#pragma unroll
        for (int tt = 0; tt < NTILE; tt++)
            sscl[tt][tid] = m[tt] * inv;
    }

    float acc[2][8][4];
#pragma unroll
    for (int i = 0; i < 2; i++)
#pragma unroll
        for (int j = 0; j < 8; j++)
#pragma unroll
            for (int r = 0; r < 4; r++) acc[i][j][r] = 0.0f;

    const int niter = K / BK64;   // 16

#pragma unroll
    for (int it = 0; it < SSTAGES - 1; it++) { ISSUE64(Ab, Bb, K, it); CP_COMMIT(); }
    __syncthreads();   // sscl ready

    const int a_row = lane & 15;
    const int a_kc = (lane >> 4) * 8;
    const int b_n = ((lane >> 4) << 3) + (lane & 7);
    const int b_kc = ((lane >> 3) & 1) * 8;

    const int R0 = wm + g, R1 = wm + g + 8, R2 = wm + 16 + g, R3 = wm + 24 + g;
    __half2 hs[4];

    for (int it = 0; it < niter; it++) {
        CP_WAIT(SSTAGES - 2);
        __syncthreads();
        if (it + SSTAGES - 1 < niter) { ISSUE64(Ab, Bb, K, it + SSTAGES - 1); }
        CP_COMMIT();

        if ((it & 1) == 0) {
            const int tt = it >> 1;
            hs[0] = __float2half2_rn(sscl[tt][R0]);
            hs[1] = __float2half2_rn(sscl[tt][R1]);
            hs[2] = __float2half2_rn(sscl[tt][R2]);
            hs[3] = __float2half2_rn(sscl[tt][R3]);
        }

        const uint32_t stg = sbase + (it % SSTAGES) * SSTAGE_B;
#pragma unroll
        for (int kk = 0; kk < BK64; kk += 16) {
            uint32_t Af[2][4];
#pragma unroll
            for (int i = 0; i < 2; i++) {
                ldsm4(Af[i], stg + (uint32_t)(wm + i * 16 + a_row) * PITCH64
                               + (uint32_t)(kk + a_kc) * 2);
                Af[i][0] = mulh2(Af[i][0], hs[2 * i]);
                Af[i][1] = mulh2(Af[i][1], hs[2 * i + 1]);
                Af[i][2] = mulh2(Af[i][2], hs[2 * i]);
                Af[i][3] = mulh2(Af[i][3], hs[2 * i + 1]);
            }
#pragma unroll
            for (int p = 0; p < 4; p++) {
                uint32_t Bf[4];
                ldsm4(Bf, stg + PLANE64 + (uint32_t)(wn + p * 16 + b_n) * PITCH64
                                        + (uint32_t)(kk + b_kc) * 2);
#pragma unroll
                for (int i = 0; i < 2; i++) {
                    mma_f16(acc[i][2 * p],     Af[i], &Bf[0]);
                    mma_f16(acc[i][2 * p + 1], Af[i], &Bf[2]);
                }
            }
        }
    }

    __half* Ch = O2 + (long long)bz * NN * HH;
    __half* Cl = Ch + sPC;
#pragma unroll
    for (int i = 0; i < 2; i++) {
        const int r0 = m0 + wm + i * 16 + g;
#pragma unroll
        for (int j = 0; j < 8; j++) {
            const int cc = n0 + wn + j * 8 + 2 * t;
            __half h0, l0, h1, l1, h2, l2, h3, l3;
            h_split(acc[i][j][0], h0, l0); h_split(acc[i][j][1], h1, l1);
            h_split(acc[i][j][2], h2, l2); h_split(acc[i][j][3], h3, l3);
            *(uint32_t*)(Ch + (long long)r0 * N + cc)       = packh2(h0, h1);
            *(uint32_t*)(Cl + (long long)r0 * N + cc)       = packh2(l0, l1);
            *(uint32_t*)(Ch + (long long)(r0 + 8) * N + cc) = packh2(h2, h3);
            *(uint32_t*)(Cl + (long long)(r0 + 8) * N + cc) = packh2(l2, l3);
        }
    }
}

// ===========================================================================
// Pair fp16 NT GEMM (3 MMAs): out = relu(o2 Wo2^T + bo), fp32 out.
// NEW: BK=64, 2 stages — half the barrier count. K-order per output unchanged.
// ===========================================================================
__global__ __launch_bounds__(THREADS) void gemm_p3(
    const __half* __restrict__ A, const __half* __restrict__ B,
    const float* __restrict__ bias, float* __restrict__ C,
    int M, int N, int K, long long sPA, long long sPB)
{
    extern __shared__ char smc[];
    const uint32_t sbase = smem_u32(smc);

    const int tid = threadIdx.x;
    const int wid = tid >> 5;
    const int lane = tid & 31;
    const int g = lane >> 2;
    const int t = lane & 3;

    const __half* Ah = A;
    const __half* Al = A + sPA;
    const __half* Bh = B;
    const __half* Bl = B + sPB;
    const int m0 = blockIdx.y * BM;
    const int n0 = blockIdx.x * BN;
    const int wm = (wid & 3) * 32;
    const int wn = (wid >> 2) * 64;

    float acc[2][8][4];
#pragma unroll
    for (int i = 0; i < 2; i++)
#pragma unroll
        for (int j = 0; j < 8; j++)
#pragma unroll
            for (int r = 0; r < 4; r++) acc[i][j][r] = 0.0f;

    const int niter = K / BK64;   // 8

    // 4 planes x 128 rows x 8 chunks = 4096 chunks; 256 thr x 16
    auto issue_loads = [&](int it) {
        const int s = it % PSTAGES;
        const int k0 = it * BK64;
        const uint32_t stg = sbase + s * PSTAGE_B;
#pragma unroll
        for (int c = 0; c < 16; c++) {
            const int id = tid + c * 256;
            const int seg = id >> 10;
            const int rid = id & 1023;
            const int row = rid >> 3, ch = rid & 7;
            const __half* src;
            int grow;
            if (seg < 2) { src = (seg == 0) ? Ah : Al; grow = m0 + row; }
            else         { src = (seg == 2) ? Bh : Bl; grow = n0 + row; }
            cp16(stg + seg * PLANE64 + row * PITCH64 + ch * 16,
                 src + (long long)grow * K + k0 + ch * 8);
        }
    };

#pragma unroll
    for (int it = 0; it < PSTAGES - 1; it++) { issue_loads(it); CP_COMMIT(); }

    const int a_row = lane & 15;
    const int a_kc = (lane >> 4) * 8;
    const int b_n = ((lane >> 4) << 3) + (lane & 7);
    const int b_kc = ((lane >> 3) & 1) * 8;

    for (int it = 0; it < niter; it++) {
        CP_WAIT(PSTAGES - 2);
        __syncthreads();
        if (it + PSTAGES - 1 < niter) issue_loads(it + PSTAGES - 1);
        CP_COMMIT();

        const uint32_t stg = sbase + (it % PSTAGES) * PSTAGE_B;
#pragma unroll
        for (int kk = 0; kk < BK64; kk += 16) {
            uint32_t Afh[2][4], Afl[2][4];
#pragma unroll
            for (int i = 0; i < 2; i++) {
                const uint32_t ao = (uint32_t)(wm + i * 16 + a_row) * PITCH64
                                  + (uint32_t)(kk + a_kc) * 2;
                ldsm4(Afh[i], stg + ao);
                ldsm4(Afl[i], stg + PLANE64 + ao);
            }
#pragma unroll
            for (int p = 0; p < 4; p++) {
                uint32_t Bfh[4], Bfl[4];
                const uint32_t bo = (uint32_t)(wn + p * 16 + b_n) * PITCH64
                                  + (uint32_t)(kk + b_kc) * 2;
                ldsm4(Bfh, stg + 2 * PLANE64 + bo);
                ldsm4(Bfl, stg + 3 * PLANE64 + bo);
#pragma unroll
                for (int i = 0; i < 2; i++) {
                    mma_f16(acc[i][2 * p],     Afh[i], &Bfh[0]);
                    mma_f16(acc[i][2 * p],     Afl[i], &Bfh[0]);
                    mma_f16(acc[i][2 * p],     Afh[i], &Bfl[0]);
                    mma_f16(acc[i][2 * p + 1], Afh[i], &Bfh[2]);
                    mma_f16(acc[i][2 * p + 1], Afl[i], &Bfh[2]);
                    mma_f16(acc[i][2 * p + 1], Afh[i], &Bfl[2]);
                }
            }
        }
    }

#pragma unroll
    for (int i = 0; i < 2; i++) {
        const int r0 = m0 + wm + i * 16 + g;
#pragma unroll
        for (int j = 0; j < 8; j++) {
            const int cc = n0 + wn + j * 8 + 2 * t;
            float b0 = bias[cc], b1 = bias[cc + 1];
            *(float2*)(C + (long long)r0 * N + cc) =
                make_float2(fmaxf(acc[i][j][0] + b0, 0.f), fmaxf(acc[i][j][1] + b1, 0.f));
            *(float2*)(C + (long long)(r0 + 8) * N + cc) =
                make_float2(fmaxf(acc[i][j][2] + b0, 0.f), fmaxf(acc[i][j][3] + b1, 0.f));
        }
    }
}

// ---------------------------------------------------------------------------
// fused pack (unchanged)
// ---------------------------------------------------------------------------
#define PK_H (HB_ELEMS / 4)
#define PK_W (W1_ELEMS / 4)
__global__ __launch_bounds__(256) void pack_all(
    const float* __restrict__ h, const float* __restrict__ Wq,
    const float* __restrict__ Wk, const float* __restrict__ Wv,
    const float* __restrict__ Wo,
    __half* __restrict__ h16, __half* __restrict__ wq16,
    __half* __restrict__ wk16, __half* __restrict__ wv16,
    __half* __restrict__ wo2)
{
    const int total = PK_H + 4 * PK_W;
    for (int i = blockIdx.x * blockDim.x + threadIdx.x; i < total;
         i += gridDim.x * blockDim.x) {
        if (i < PK_H + 3 * PK_W) {
            const float* src; __half* dst; int idx;
            if (i < PK_H) { src = h; dst = h16; idx = i; }
            else {
                int r = i - PK_H;
                int seg = r / PK_W; idx = r % PK_W;
                src = (seg == 0) ? Wq : (seg == 1) ? Wk : Wv;
                dst = (seg == 0) ? wq16 : (seg == 1) ? wk16 : wv16;
            }
            float4 v = ((const float4*)src)[idx];
            ((uint2*)dst)[idx] = make_uint2(
                packh2(__float2half_rn(v.x), __float2half_rn(v.y)),
                packh2(__float2half_rn(v.z), __float2half_rn(v.w)));
        } else {
            int idx = i - PK_H - 3 * PK_W;
            float4 v = ((const float4*)Wo)[idx];
            __half h0, l0, h1, l1, h2, l2, h3, l3;
            h_split(v.x, h0, l0); h_split(v.y, h1, l1);
            h_split(v.z, h2, l2); h_split(v.w, h3, l3);
            ((uint2*)wo2)[idx] = make_uint2(packh2(h0, h1), packh2(h2, h3));
            ((uint2*)(wo2 + 2 * W1_ELEMS))[idx] = make_uint2(packh2(l0, l1), packh2(l2, l3));
        }
    }
}

// ---------------------------------------------------------------------------
// kernel_launch — inputs: h, Wv, bv, Wk, bk, Wq, bq, Wo, bo
// ---------------------------------------------------------------------------
extern "C" void kernel_launch(void* const* d_in, const int* in_sizes, int n_in,
                              void* d_out, int out_size)
{
    const float* h  = (const float*)d_in[0];
    const float* Wv = (const float*)d_in[1];
    const float* bv = (const float*)d_in[2];
    const float* Wk = (const float*)d_in[3];
    const float* bk = (const float*)d_in[4];
    const float* Wq = (const float*)d_in[5];
    const float* bq = (const float*)d_in[6];
    const float* Wo = (const float*)d_in[7];
    const float* bo = (const float*)d_in[8];
    float* out = (float*)d_out;

    __half *h16, *wq16, *wk16, *wv16, *wo2, *q, *k, *vt, *e, *o2;
    float *mloc, *rsum;
    cudaGetSymbolAddress((void**)&h16,  g_h16);
    cudaGetSymbolAddress((void**)&wq16, g_wq16);
    cudaGetSymbolAddress((void**)&wk16, g_wk16);
    cudaGetSymbolAddress((void**)&wv16, g_wv16);
    cudaGetSymbolAddress((void**)&wo2,  g_wo2);
    cudaGetSymbolAddress((void**)&q,    g_q);
    cudaGetSymbolAddress((void**)&k,    g_k);
    cudaGetSymbolAddress((void**)&vt,   g_vt);
    cudaGetSymbolAddress((void**)&e,    g_e);
    cudaGetSymbolAddress((void**)&mloc, g_mloc);
    cudaGetSymbolAddress((void**)&rsum, g_rsum);
    cudaGetSymbolAddress((void**)&o2,   g_o2);

    cudaFuncSetAttribute(gemm_proj, cudaFuncAttributeMaxDynamicSharedMemorySize, SSMEM);
    cudaFuncSetAttribute(gemm_qk,   cudaFuncAttributeMaxDynamicSharedMemorySize, SSMEM);
    cudaFuncSetAttribute(gemm_pv,   cudaFuncAttributeMaxDynamicSharedMemorySize, SSMEM);
    cudaFuncSetAttribute(gemm_p3,   cudaFuncAttributeMaxDynamicSharedMemorySize, PSMEM);

    const int M = BB * NN;   // 32768

    // 1. fused pack
    pack_all<<<2048, 256>>>(h, Wq, Wk, Wv, Wo, h16, wq16, wk16, wv16, wo2);

    // 2. fused Q/K/V projections; z==2 writes vt directly
    {
        dim3 grid(HH / BN, M / BM, 3);
        gemm_proj<<<grid, THREADS, SSMEM>>>(h16, wq16, wk16, wv16,
                                            bq, bk, bv, q, k, vt);
    }

    // 3. S GEMM + online exp -> e fp16 + per-tile stats
    {
        dim3 grid(NN / BN, NN / BM, BB);
        gemm_qk<<<grid, THREADS, SSMEM>>>(q, k, e, mloc, rsum);
    }

    // 4. O = scaled-E * Vt^T -> fp16 pair (stats inlined)
    {
        dim3 grid(HH / BN, NN / BM, BB);
        gemm_pv<<<grid, THREADS, SSMEM>>>(e, vt, mloc, rsum, o2, QKV_ELEMS);
    }

    // 5. out = relu(O Wo^T + bo) -> fp32
    {
        dim3 grid(DD / BN, M / BM, 1);
        gemm_p3<<<grid, THREADS, PSMEM>>>(o2, wo2, bo, out, M, DD, HH,
                                          QKV_ELEMS, W1_ELEMS);
    }
}

// round 13
// speedup vs baseline: 1.1169x; 1.0745x over previous
#include <cuda_runtime.h>
#include <cuda_fp16.h>
#include <cstdint>

// Problem dims
#define BB 32
#define NN 1024
#define DD 256
#define HH 512
#define HB_ELEMS (BB * NN * DD)
#define QKV_ELEMS (BB * NN * HH)
#define S_ELEMS ((long long)BB * NN * NN)
#define W1_ELEMS (HH * DD)
#define NTILE 8

// ---------------- scratch ----------------
__device__ __half g_h16[HB_ELEMS];
__device__ __half g_wq16[W1_ELEMS], g_wk16[W1_ELEMS], g_wv16[W1_ELEMS];
__device__ __half g_wo16[W1_ELEMS];             // Wo hi plane only
__device__ __half g_q[QKV_ELEMS], g_k[QKV_ELEMS];
__device__ __half g_vt[QKV_ELEMS];              // [b][h][n]
__device__ __half g_e[S_ELEMS];
__device__ float  g_mloc[BB * NTILE * NN];
__device__ float  g_rsum[BB * NTILE * NN];
__device__ __half g_o2[2 * QKV_ELEMS];          // o pair (hi, lo)

// ---------------- helpers ----------------
__device__ __forceinline__ void h_split(float x, __half& h, __half& l) {
    h = __float2half_rn(x);
    l = __float2half_rn(x - __half2float(h));
}
__device__ __forceinline__ uint32_t packh2(__half a, __half b) {
    __half2 t = __halves2half2(a, b);
    return *reinterpret_cast<uint32_t*>(&t);
}
__device__ __forceinline__ uint32_t mulh2(uint32_t a, __half2 s) {
    __half2 x = *reinterpret_cast<__half2*>(&a);
    x = __hmul2(x, s);
    return *reinterpret_cast<uint32_t*>(&x);
}
__device__ __forceinline__ uint32_t smem_u32(const void* p) {
    uint32_t a;
    asm("{ .reg .u64 t; cvta.to.shared.u64 t, %1; cvt.u32.u64 %0, t; }" : "=r"(a) : "l"(p));
    return a;
}
__device__ __forceinline__ void cp16(uint32_t dst, const void* src) {
    asm volatile("cp.async.cg.shared.global [%0], [%1], 16;" :: "r"(dst), "l"(src));
}
#define CP_COMMIT() asm volatile("cp.async.commit_group;" ::: "memory")
#define CP_WAIT(n)  asm volatile("cp.async.wait_group %0;" :: "n"(n) : "memory")

__device__ __forceinline__ void ldsm4(uint32_t* r, uint32_t addr) {
    asm volatile("ldmatrix.sync.aligned.m8n8.x4.shared.b16 {%0,%1,%2,%3}, [%4];"
        : "=r"(r[0]), "=r"(r[1]), "=r"(r[2]), "=r"(r[3]) : "r"(addr));
}
__device__ __forceinline__ void mma_f16(float* d, const uint32_t* a, const uint32_t* b) {
    asm volatile(
        "mma.sync.aligned.m16n8k16.row.col.f32.f16.f16.f32 "
        "{%0,%1,%2,%3}, {%4,%5,%6,%7}, {%8,%9}, {%0,%1,%2,%3};"
        : "+f"(d[0]), "+f"(d[1]), "+f"(d[2]), "+f"(d[3])
        : "r"(a[0]), "r"(a[1]), "r"(a[2]), "r"(a[3]), "r"(b[0]), "r"(b[1]));
}

// ---------------- tile config ----------------
#define BM 128
#define BN 128
#define THREADS 256

// single-plane GEMMs: BK=64, pitch 144 B, 3 stages, 2 CTAs/SM
#define BK64 64
#define PITCH64 144
#define PLANE64 (128 * PITCH64)          // 18432 B
#define SSTAGES 3
#define SSTAGE_B (2 * PLANE64)           // 36864
#define SSMEM (SSTAGES * SSTAGE_B)       // 110592

// p3 GEMM (out-proj, 2-MMA): 3 planes (Ah, Al, B), BK=64, 2 stages, 2 CTAs/SM
#define P3STAGES 2
#define P3STAGE_B (3 * PLANE64)          // 55296
#define P3SMEM (P3STAGES * P3STAGE_B)    // 110592

// transposed-epilogue staging pitch (halves)
#define PT 132

// ---- mainloop load macro (BK=64 single-plane, 256 threads) ----
#define ISSUE64(Ab, Bb, Kdim, it)                                              \
    do {                                                                       \
        const int s_ = (it) % SSTAGES;                                         \
        const int k0_ = (it) * BK64;                                           \
        const uint32_t stg_ = sbase + s_ * SSTAGE_B;                           \
        _Pragma("unroll")                                                      \
        for (int c_ = 0; c_ < 8; c_++) {                                       \
            const int id_ = tid + c_ * 256;                                    \
            const int seg_ = id_ >> 10;                                        \
            const int rid_ = id_ & 1023;                                       \
            const int row_ = rid_ >> 3, ch_ = rid_ & 7;                        \
            const __half* src_ = seg_ ? (Bb + (long long)(n0 + row_) * Kdim)   \
                                      : (Ab + (long long)(m0 + row_) * Kdim);  \
            cp16(stg_ + seg_ * PLANE64 + row_ * PITCH64 + ch_ * 16,            \
                 src_ + k0_ + ch_ * 8);                                        \
        }                                                                      \
    } while (0)

// ===========================================================================
// Fused Q/K/V projection (8 warps, 32x64 warp tiles)
// ===========================================================================
__global__ __launch_bounds__(THREADS, 2) void gemm_proj(
    const __half* __restrict__ Hm,
    const __half* __restrict__ Wqp, const __half* __restrict__ Wkp,
    const __half* __restrict__ Wvp,
    const float* __restrict__ bqp, const float* __restrict__ bkp,
    const float* __restrict__ bvp,
    __half* __restrict__ Qp, __half* __restrict__ Kp, __half* __restrict__ Vtp)
{
    extern __shared__ char smc[];
    const uint32_t sbase = smem_u32(smc);

    const int tid = threadIdx.x;
    const int wid = tid >> 5;
    const int lane = tid & 31;
    const int g = lane >> 2;
    const int t = lane & 3;
    const int z = blockIdx.z;

    const __half* Ab = Hm;
    const __half* Bb = (z == 0) ? Wqp : (z == 1) ? Wkp : Wvp;
    const float* bias = (z == 0) ? bqp : (z == 1) ? bkp : bvp;

    const int m0 = blockIdx.y * BM;
    const int n0 = blockIdx.x * BN;
    const int wm = (wid & 3) * 32;
    const int wn = (wid >> 2) * 64;
    const int K = DD, N = HH;

    float acc[2][8][4];
#pragma unroll
    for (int i = 0; i < 2; i++)
#pragma unroll
        for (int j = 0; j < 8; j++)
#pragma unroll
            for (int r = 0; r < 4; r++) acc[i][j][r] = 0.0f;

    const int niter = K / BK64;     // 4

#pragma unroll
    for (int it = 0; it < SSTAGES - 1; it++) { ISSUE64(Ab, Bb, K, it); CP_COMMIT(); }

    const int a_row = lane & 15;
    const int a_kc = (lane >> 4) * 8;
    const int b_n = ((lane >> 4) << 3) + (lane & 7);
    const int b_kc = ((lane >> 3) & 1) * 8;

    for (int it = 0; it < niter; it++) {
        CP_WAIT(SSTAGES - 2);
        __syncthreads();
        if (it + SSTAGES - 1 < niter) { ISSUE64(Ab, Bb, K, it + SSTAGES - 1); }
        CP_COMMIT();

        const uint32_t stg = sbase + (it % SSTAGES) * SSTAGE_B;
#pragma unroll
        for (int kk = 0; kk < BK64; kk += 16) {
            uint32_t Af[2][4];
#pragma unroll
            for (int i = 0; i < 2; i++)
                ldsm4(Af[i], stg + (uint32_t)(wm + i * 16 + a_row) * PITCH64
                               + (uint32_t)(kk + a_kc) * 2);
#pragma unroll
            for (int p = 0; p < 4; p++) {
                uint32_t Bf[4];
                ldsm4(Bf, stg + PLANE64 + (uint32_t)(wn + p * 16 + b_n) * PITCH64
                                        + (uint32_t)(kk + b_kc) * 2);
#pragma unroll
                for (int i = 0; i < 2; i++) {
                    mma_f16(acc[i][2 * p],     Af[i], &Bf[0]);
                    mma_f16(acc[i][2 * p + 1], Af[i], &Bf[2]);
                }
            }
        }
    }

    if (z < 2) {
        __half* C = (z == 0) ? Qp : Kp;
#pragma unroll
        for (int i = 0; i < 2; i++) {
            const int r0 = m0 + wm + i * 16 + g;
#pragma unroll
            for (int j = 0; j < 8; j++) {
                const int cc = n0 + wn + j * 8 + 2 * t;
                float b0 = bias[cc], b1 = bias[cc + 1];
                float x0 = fmaxf(acc[i][j][0] + b0, 0.f);
                float x1 = fmaxf(acc[i][j][1] + b1, 0.f);
                float x2 = fmaxf(acc[i][j][2] + b0, 0.f);
                float x3 = fmaxf(acc[i][j][3] + b1, 0.f);
                *(uint32_t*)(C + (long long)r0 * N + cc) =
                    packh2(__float2half_rn(x0), __float2half_rn(x1));
                *(uint32_t*)(C + (long long)(r0 + 8) * N + cc) =
                    packh2(__float2half_rn(x2), __float2half_rn(x3));
            }
        }
    } else {
        // V: stage tile in smem, write transposed vt[b][h][n]
        __syncthreads();
        __half* tile = (__half*)smc;
#pragma unroll
        for (int i = 0; i < 2; i++) {
            const int rl0 = wm + i * 16 + g;
#pragma unroll
            for (int j = 0; j < 8; j++) {
                const int cl = wn + j * 8 + 2 * t;
                float b0 = bias[n0 + cl], b1 = bias[n0 + cl + 1];
                tile[rl0 * PT + cl]           = __float2half_rn(fmaxf(acc[i][j][0] + b0, 0.f));
                tile[rl0 * PT + cl + 1]       = __float2half_rn(fmaxf(acc[i][j][1] + b1, 0.f));
                tile[(rl0 + 8) * PT + cl]     = __float2half_rn(fmaxf(acc[i][j][2] + b0, 0.f));
                tile[(rl0 + 8) * PT + cl + 1] = __float2half_rn(fmaxf(acc[i][j][3] + b1, 0.f));
            }
        }
        __syncthreads();
        const int b = m0 >> 10;
        const int nloc = m0 & 1023;
        __half* vtb = Vtp + (long long)b * HH * NN + nloc;
        const int g2 = tid >> 7;
        const int l128 = tid & 127;
#pragma unroll
        for (int jc = 0; jc < 64; jc++) {
            const int c = g2 * 64 + jc;
            vtb[(long long)(n0 + c) * NN + l128] = tile[l128 * PT + c];
        }
    }
}

// ===========================================================================
// S GEMM with online-exp epilogue (8 warps, 32x64)
// ===========================================================================
__global__ __launch_bounds__(THREADS, 2) void gemm_qk(
    const __half* __restrict__ Q, const __half* __restrict__ Kx,
    __half* __restrict__ E, float* __restrict__ mloc, float* __restrict__ rsum)
{
    extern __shared__ char smc[];
    __shared__ float sred[2][128];
    const uint32_t sbase = smem_u32(smc);

    const int tid = threadIdx.x;
    const int wid = tid >> 5;
    const int lane = tid & 31;
    const int g = lane >> 2;
    const int t = lane & 3;
    const int bz = blockIdx.z;

    const __half* Ab = Q + ((long long)bz * NN * HH);
    const __half* Bb = Kx + ((long long)bz * NN * HH);
    const int m0 = blockIdx.y * BM;
    const int n0 = blockIdx.x * BN;
    const int wm = (wid & 3) * 32;
    const int wn = (wid >> 2) * 64;
    const int K = HH;

    float acc[2][8][4];
#pragma unroll
    for (int i = 0; i < 2; i++)
#pragma unroll
        for (int j = 0; j < 8; j++)
#pragma unroll
            for (int r = 0; r < 4; r++) acc[i][j][r] = 0.0f;

    const int niter = K / BK64;   // 8

#pragma unroll
    for (int it = 0; it < SSTAGES - 1; it++) { ISSUE64(Ab, Bb, K, it); CP_COMMIT(); }

    const int a_row = lane & 15;
    const int a_kc = (lane >> 4) * 8;
    const int b_n = ((lane >> 4) << 3) + (lane & 7);
    const int b_kc = ((lane >> 3) & 1) * 8;

    for (int it = 0; it < niter; it++) {
        CP_WAIT(SSTAGES - 2);
        __syncthreads();
        if (it + SSTAGES - 1 < niter) { ISSUE64(Ab, Bb, K, it + SSTAGES - 1); }
        CP_COMMIT();

        const uint32_t stg = sbase + (it % SSTAGES) * SSTAGE_B;
#pragma unroll
        for (int kk = 0; kk < BK64; kk += 16) {
            uint32_t Af[2][4];
#pragma unroll
            for (int i = 0; i < 2; i++)
                ldsm4(Af[i], stg + (uint32_t)(wm + i * 16 + a_row) * PITCH64
                               + (uint32_t)(kk + a_kc) * 2);
#pragma unroll
            for (int p = 0; p < 4; p++) {
                uint32_t Bf[4];
                ldsm4(Bf, stg + PLANE64 + (uint32_t)(wn + p * 16 + b_n) * PITCH64
                                        + (uint32_t)(kk + b_kc) * 2);
#pragma unroll
                for (int i = 0; i < 2; i++) {
                    mma_f16(acc[i][2 * p],     Af[i], &Bf[0]);
                    mma_f16(acc[i][2 * p + 1], Af[i], &Bf[2]);
                }
            }
        }
    }

    // ---- online-exp epilogue (bit-exact order) ----
    const int R0 = wm + g, R1 = wm + g + 8, R2 = wm + 16 + g, R3 = wm + 24 + g;
    const int half = wid >> 2;

    float rm[4] = {-1e30f, -1e30f, -1e30f, -1e30f};
#pragma unroll
    for (int j = 0; j < 8; j++) {
        rm[0] = fmaxf(rm[0], fmaxf(acc[0][j][0], acc[0][j][1]));
        rm[1] = fmaxf(rm[1], fmaxf(acc[0][j][2], acc[0][j][3]));
        rm[2] = fmaxf(rm[2], fmaxf(acc[1][j][0], acc[1][j][1]));
        rm[3] = fmaxf(rm[3], fmaxf(acc[1][j][2], acc[1][j][3]));
    }
#pragma unroll
    for (int o = 1; o <= 2; o <<= 1)
#pragma unroll
        for (int k = 0; k < 4; k++)
            rm[k] = fmaxf(rm[k], __shfl_xor_sync(0xffffffffu, rm[k], o));

    __syncthreads();
    if (t == 0) {
        sred[half][R0] = rm[0]; sred[half][R1] = rm[1];
        sred[half][R2] = rm[2]; sred[half][R3] = rm[3];
    }
    __syncthreads();
    float gm[4];
    gm[0] = fmaxf(sred[0][R0], sred[1][R0]);
    gm[1] = fmaxf(sred[0][R1], sred[1][R1]);
    gm[2] = fmaxf(sred[0][R2], sred[1][R2]);
    gm[3] = fmaxf(sred[0][R3], sred[1][R3]);
    __syncthreads();

    float rs[4] = {0.f, 0.f, 0.f, 0.f};
#pragma unroll
    for (int j = 0; j < 8; j++) {
        acc[0][j][0] = __expf(acc[0][j][0] - gm[0]);
        acc[0][j][1] = __expf(acc[0][j][1] - gm[0]);
        rs[0] += acc[0][j][0] + acc[0][j][1];
        acc[0][j][2] = __expf(acc[0][j][2] - gm[1]);
        acc[0][j][3] = __expf(acc[0][j][3] - gm[1]);
        rs[1] += acc[0][j][2] + acc[0][j][3];
        acc[1][j][0] = __expf(acc[1][j][0] - gm[2]);
        acc[1][j][1] = __expf(acc[1][j][1] - gm[2]);
        rs[2] += acc[1][j][0] + acc[1][j][1];
        acc[1][j][2] = __expf(acc[1][j][2] - gm[3]);
        acc[1][j][3] = __expf(acc[1][j][3] - gm[3]);
        rs[3] += acc[1][j][2] + acc[1][j][3];
    }
#pragma unroll
    for (int o = 1; o <= 2; o <<= 1)
#pragma unroll
        for (int k = 0; k < 4; k++)
            rs[k] += __shfl_xor_sync(0xffffffffu, rs[k], o);

    if (t == 0 && half == 0) {
        sred[0][R0] = rs[0]; sred[0][R1] = rs[1];
        sred[0][R2] = rs[2]; sred[0][R3] = rs[3];
    }
    __syncthreads();
    if (t == 0 && half == 1) {
        atomicAdd(&sred[0][R0], rs[0]); atomicAdd(&sred[0][R1], rs[1]);
        atomicAdd(&sred[0][R2], rs[2]); atomicAdd(&sred[0][R3], rs[3]);
    }
    __syncthreads();

    if (t == 0 && half == 0) {
        const long long sb = ((long long)(bz * NTILE + blockIdx.x) << 10) + m0;
        mloc[sb + R0] = gm[0]; rsum[sb + R0] = sred[0][R0];
        mloc[sb + R1] = gm[1]; rsum[sb + R1] = sred[0][R1];
        mloc[sb + R2] = gm[2]; rsum[sb + R2] = sred[0][R2];
        mloc[sb + R3] = gm[3]; rsum[sb + R3] = sred[0][R3];
    }

    __half* Eb = E + ((long long)bz << 20);
#pragma unroll
    for (int i = 0; i < 2; i++) {
        const int r0 = m0 + wm + i * 16 + g;
#pragma unroll
        for (int j = 0; j < 8; j++) {
            const int cc = n0 + wn + j * 8 + 2 * t;
            *(uint32_t*)(Eb + (long long)r0 * NN + cc) =
                packh2(__float2half_rn(acc[i][j][0]), __float2half_rn(acc[i][j][1]));
            *(uint32_t*)(Eb + (long long)(r0 + 8) * NN + cc) =
                packh2(__float2half_rn(acc[i][j][2]), __float2half_rn(acc[i][j][3]));
        }
    }
}

// ===========================================================================
// O GEMM: O = (diag-scaled E) * Vt^T -> half-pair, stats inlined
// ===========================================================================
__global__ __launch_bounds__(THREADS, 2) void gemm_pv(
    const __half* __restrict__ E, const __half* __restrict__ Vt,
    const float* __restrict__ mloc, const float* __restrict__ rsum,
    __half* __restrict__ O2, long long sPC)
{
    extern __shared__ char smc[];
    __shared__ float sscl[NTILE][128];
    const uint32_t sbase = smem_u32(smc);

    const int tid = threadIdx.x;
    const int wid = tid >> 5;
    const int lane = tid & 31;
    const int g = lane >> 2;
    const int t = lane & 3;
    const int bz = blockIdx.z;

    const __half* Ab = E + ((long long)bz << 20);
    const __half* Bb = Vt + ((long long)bz * HH * NN);
    const int m0 = blockIdx.y * BM;
    const int n0 = blockIdx.x * BN;
    const int wm = (wid & 3) * 32;
    const int wn = (wid >> 2) * 64;
    const int N = HH, K = NN;

    // inline stats (identical op order)
    if (tid < 128) {
        const int r = m0 + tid;
        float m[NTILE], s[NTILE];
        float M = -1e30f;
#pragma unroll
        for (int tt = 0; tt < NTILE; tt++) {
            const long long p = ((long long)(bz * NTILE + tt) << 10) + r;
            m[tt] = mloc[p]; s[tt] = rsum[p];
            M = fmaxf(M, m[tt]);
        }
        float denom = 0.f;
#pragma unroll
        for (int tt = 0; tt < NTILE; tt++) {
            m[tt] = __expf(m[tt] - M);
            denom += s[tt] * m[tt];
        }
        const float inv = 1.0f / denom;
#pragma unroll
        for (int tt = 0; tt < NTILE; tt++)
            sscl[tt][tid] = m[tt] * inv;
    }

    float acc[2][8][4];
#pragma unroll
    for (int i = 0; i < 2; i++)
#pragma unroll
        for (int j = 0; j < 8; j++)
#pragma unroll
            for (int r = 0; r < 4; r++) acc[i][j][r] = 0.0f;

    const int niter = K / BK64;   // 16

#pragma unroll
    for (int it = 0; it < SSTAGES - 1; it++) { ISSUE64(Ab, Bb, K, it); CP_COMMIT(); }
    __syncthreads();   // sscl ready

    const int a_row = lane & 15;
    const int a_kc = (lane >> 4) * 8;
    const int b_n = ((lane >> 4) << 3) + (lane & 7);
    const int b_kc = ((lane >> 3) & 1) * 8;

    const int R0 = wm + g, R1 = wm + g + 8, R2 = wm + 16 + g, R3 = wm + 24 + g;
    __half2 hs[4];

    for (int it = 0; it < niter; it++) {
        CP_WAIT(SSTAGES - 2);
        __syncthreads();
        if (it + SSTAGES - 1 < niter) { ISSUE64(Ab, Bb, K, it + SSTAGES - 1); }
        CP_COMMIT();

        if ((it & 1) == 0) {
            const int tt = it >> 1;
            hs[0] = __float2half2_rn(sscl[tt][R0]);
            hs[1] = __float2half2_rn(sscl[tt][R1]);
            hs[2] = __float2half2_rn(sscl[tt][R2]);
            hs[3] = __float2half2_rn(sscl[tt][R3]);
        }

        const uint32_t stg = sbase + (it % SSTAGES) * SSTAGE_B;
#pragma unroll
        for (int kk = 0; kk < BK64; kk += 16) {
            uint32_t Af[2][4];
#pragma unroll
            for (int i = 0; i < 2; i++) {
                ldsm4(Af[i], stg + (uint32_t)(wm + i * 16 + a_row) * PITCH64
                               + (uint32_t)(kk + a_kc) * 2);
                Af[i][0] = mulh2(Af[i][0], hs[2 * i]);
                Af[i][1] = mulh2(Af[i][1], hs[2 * i + 1]);
                Af[i][2] = mulh2(Af[i][2], hs[2 * i]);
                Af[i][3] = mulh2(Af[i][3], hs[2 * i + 1]);
            }
#pragma unroll
            for (int p = 0; p < 4; p++) {
                uint32_t Bf[4];
                ldsm4(Bf, stg + PLANE64 + (uint32_t)(wn + p * 16 + b_n) * PITCH64
                                        + (uint32_t)(kk + b_kc) * 2);
#pragma unroll
                for (int i = 0; i < 2; i++) {
                    mma_f16(acc[i][2 * p],     Af[i], &Bf[0]);
                    mma_f16(acc[i][2 * p + 1], Af[i], &Bf[2]);
                }
            }
        }
    }

    __half* Ch = O2 + (long long)bz * NN * HH;
    __half* Cl = Ch + sPC;
#pragma unroll
    for (int i = 0; i < 2; i++) {
        const int r0 = m0 + wm + i * 16 + g;
#pragma unroll
        for (int j = 0; j < 8; j++) {
            const int cc = n0 + wn + j * 8 + 2 * t;
            __half h0, l0, h1, l1, h2, l2, h3, l3;
            h_split(acc[i][j][0], h0, l0); h_split(acc[i][j][1], h1, l1);
            h_split(acc[i][j][2], h2, l2); h_split(acc[i][j][3], h3, l3);
            *(uint32_t*)(Ch + (long long)r0 * N + cc)       = packh2(h0, h1);
            *(uint32_t*)(Cl + (long long)r0 * N + cc)       = packh2(l0, l1);
            *(uint32_t*)(Ch + (long long)(r0 + 8) * N + cc) = packh2(h2, h3);
            *(uint32_t*)(Cl + (long long)(r0 + 8) * N + cc) = packh2(l2, l3);
        }
    }
}

// ===========================================================================
// Out-proj GEMM (2 MMAs): out = relu((o_hi + o_lo) Wo_hi^T + bo), fp32 out.
// A = o pair (hi, lo at sPA), B = Wo hi plane. BK=64, 2 stages, 2 CTAs/SM.
// Bit-exact vs prior: removes only the Ah*Bl term whose Bl was all zeros.
// ===========================================================================
__global__ __launch_bounds__(THREADS, 2) void gemm_p3(
    const __half* __restrict__ A, const __half* __restrict__ B,
    const float* __restrict__ bias, float* __restrict__ C,
    int M, int N, int K, long long sPA)
{
    extern __shared__ char smc[];
    const uint32_t sbase = smem_u32(smc);

    const int tid = threadIdx.x;
    const int wid = tid >> 5;
    const int lane = tid & 31;
    const int g = lane >> 2;
    const int t = lane & 3;

    const __half* Ah = A;
    const __half* Al = A + sPA;
    const int m0 = blockIdx.y * BM;
    const int n0 = blockIdx.x * BN;
    const int wm = (wid & 3) * 32;
    const int wn = (wid >> 2) * 64;

    float acc[2][8][4];
#pragma unroll
    for (int i = 0; i < 2; i++)
#pragma unroll
        for (int j = 0; j < 8; j++)
#pragma unroll
            for (int r = 0; r < 4; r++) acc[i][j][r] = 0.0f;

    const int niter = K / BK64;   // 8

    // 3 planes x 128 rows x 8 chunks = 3072 chunks; 256 thr x 12
    auto issue_loads = [&](int it) {
        const int s = it % P3STAGES;
        const int k0 = it * BK64;
        const uint32_t stg = sbase + s * P3STAGE_B;
#pragma unroll
        for (int c = 0; c < 12; c++) {
            const int id = tid + c * 256;
            const int seg = id >> 10;
            const int rid = id & 1023;
            const int row = rid >> 3, ch = rid & 7;
            const __half* src = (seg == 0) ? (Ah + (long long)(m0 + row) * K)
                              : (seg == 1) ? (Al + (long long)(m0 + row) * K)
                                           : (B  + (long long)(n0 + row) * K);
            cp16(stg + seg * PLANE64 + row * PITCH64 + ch * 16,
                 src + k0 + ch * 8);
        }
    };

#pragma unroll
    for (int it = 0; it < P3STAGES - 1; it++) { issue_loads(it); CP_COMMIT(); }

    const int a_row = lane & 15;
    const int a_kc = (lane >> 4) * 8;
    const int b_n = ((lane >> 4) << 3) + (lane & 7);
    const int b_kc = ((lane >> 3) & 1) * 8;

    for (int it = 0; it < niter; it++) {
        CP_WAIT(P3STAGES - 2);
        __syncthreads();
        if (it + P3STAGES - 1 < niter) issue_loads(it + P3STAGES - 1);
        CP_COMMIT();

        const uint32_t stg = sbase + (it % P3STAGES) * P3STAGE_B;
#pragma unroll
        for (int kk = 0; kk < BK64; kk += 16) {
            uint32_t Afh[2][4], Afl[2][4];
#pragma unroll
            for (int i = 0; i < 2; i++) {
                const uint32_t ao = (uint32_t)(wm + i * 16 + a_row) * PITCH64
                                  + (uint32_t)(kk + a_kc) * 2;
                ldsm4(Afh[i], stg + ao);
                ldsm4(Afl[i], stg + PLANE64 + ao);
            }
#pragma unroll
            for (int p = 0; p < 4; p++) {
                uint32_t Bf[4];
                ldsm4(Bf, stg + 2 * PLANE64
                         + (uint32_t)(wn + p * 16 + b_n) * PITCH64
                         + (uint32_t)(kk + b_kc) * 2);
#pragma unroll
                for (int i = 0; i < 2; i++) {
                    mma_f16(acc[i][2 * p],     Afh[i], &Bf[0]);
                    mma_f16(acc[i][2 * p],     Afl[i], &Bf[0]);
                    mma_f16(acc[i][2 * p + 1], Afh[i], &Bf[2]);
                    mma_f16(acc[i][2 * p + 1], Afl[i], &Bf[2]);
                }
            }
        }
    }

#pragma unroll
    for (int i = 0; i < 2; i++) {
        const int r0 = m0 + wm + i * 16 + g;
#pragma unroll
        for (int j = 0; j < 8; j++) {
            const int cc = n0 + wn + j * 8 + 2 * t;
            float b0 = bias[cc], b1 = bias[cc + 1];
            *(float2*)(C + (long long)r0 * N + cc) =
                make_float2(fmaxf(acc[i][j][0] + b0, 0.f), fmaxf(acc[i][j][1] + b1, 0.f));
            *(float2*)(C + (long long)(r0 + 8) * N + cc) =
                make_float2(fmaxf(acc[i][j][2] + b0, 0.f), fmaxf(acc[i][j][3] + b1, 0.f));
        }
    }
}

// ---------------------------------------------------------------------------
// fused pack: h + all 4 weights -> fp16 (single plane each; no OOB)
// ---------------------------------------------------------------------------
#define PK_H (HB_ELEMS / 4)
#define PK_W (W1_ELEMS / 4)
__global__ __launch_bounds__(256) void pack_all(
    const float* __restrict__ h, const float* __restrict__ Wq,
    const float* __restrict__ Wk, const float* __restrict__ Wv,
    const float* __restrict__ Wo,
    __half* __restrict__ h16, __half* __restrict__ wq16,
    __half* __restrict__ wk16, __half* __restrict__ wv16,
    __half* __restrict__ wo16)
{
    const int total = PK_H + 4 * PK_W;
    for (int i = blockIdx.x * blockDim.x + threadIdx.x; i < total;
         i += gridDim.x * blockDim.x) {
        const float* src; __half* dst; int idx;
        if (i < PK_H) { src = h; dst = h16; idx = i; }
        else {
            int r = i - PK_H;
            int seg = r / PK_W; idx = r % PK_W;
            src = (seg == 0) ? Wq : (seg == 1) ? Wk : (seg == 2) ? Wv : Wo;
            dst = (seg == 0) ? wq16 : (seg == 1) ? wk16 : (seg == 2) ? wv16 : wo16;
        }
        float4 v = ((const float4*)src)[idx];
        ((uint2*)dst)[idx] = make_uint2(
            packh2(__float2half_rn(v.x), __float2half_rn(v.y)),
            packh2(__float2half_rn(v.z), __float2half_rn(v.w)));
    }
}

// ---------------------------------------------------------------------------
// kernel_launch — inputs: h, Wv, bv, Wk, bk, Wq, bq, Wo, bo
// ---------------------------------------------------------------------------
extern "C" void kernel_launch(void* const* d_in, const int* in_sizes, int n_in,
                              void* d_out, int out_size)
{
    const float* h  = (const float*)d_in[0];
    const float* Wv = (const float*)d_in[1];
    const float* bv = (const float*)d_in[2];
    const float* Wk = (const float*)d_in[3];
    const float* bk = (const float*)d_in[4];
    const float* Wq = (const float*)d_in[5];
    const float* bq = (const float*)d_in[6];
    const float* Wo = (const float*)d_in[7];
    const float* bo = (const float*)d_in[8];
    float* out = (float*)d_out;

    __half *h16, *wq16, *wk16, *wv16, *wo16, *q, *k, *vt, *e, *o2;
    float *mloc, *rsum;
    cudaGetSymbolAddress((void**)&h16,  g_h16);
    cudaGetSymbolAddress((void**)&wq16, g_wq16);
    cudaGetSymbolAddress((void**)&wk16, g_wk16);
    cudaGetSymbolAddress((void**)&wv16, g_wv16);
    cudaGetSymbolAddress((void**)&wo16, g_wo16);
    cudaGetSymbolAddress((void**)&q,    g_q);
    cudaGetSymbolAddress((void**)&k,    g_k);
    cudaGetSymbolAddress((void**)&vt,   g_vt);
    cudaGetSymbolAddress((void**)&e,    g_e);
    cudaGetSymbolAddress((void**)&mloc, g_mloc);
    cudaGetSymbolAddress((void**)&rsum, g_rsum);
    cudaGetSymbolAddress((void**)&o2,   g_o2);

    cudaFuncSetAttribute(gemm_proj, cudaFuncAttributeMaxDynamicSharedMemorySize, SSMEM);
    cudaFuncSetAttribute(gemm_qk,   cudaFuncAttributeMaxDynamicSharedMemorySize, SSMEM);
    cudaFuncSetAttribute(gemm_pv,   cudaFuncAttributeMaxDynamicSharedMemorySize, SSMEM);
    cudaFuncSetAttribute(gemm_p3,   cudaFuncAttributeMaxDynamicSharedMemorySize, P3SMEM);

    const int M = BB * NN;   // 32768

    // 1. fused pack
    pack_all<<<2048, 256>>>(h, Wq, Wk, Wv, Wo, h16, wq16, wk16, wv16, wo16);

    // 2. fused Q/K/V projections; z==2 writes vt directly
    {
        dim3 grid(HH / BN, M / BM, 3);
        gemm_proj<<<grid, THREADS, SSMEM>>>(h16, wq16, wk16, wv16,
                                            bq, bk, bv, q, k, vt);
    }

    // 3. S GEMM + online exp -> e fp16 + per-tile stats
    {
        dim3 grid(NN / BN, NN / BM, BB);
        gemm_qk<<<grid, THREADS, SSMEM>>>(q, k, e, mloc, rsum);
    }

    // 4. O = scaled-E * Vt^T -> fp16 pair (stats inlined)
    {
        dim3 grid(HH / BN, NN / BM, BB);
        gemm_pv<<<grid, THREADS, SSMEM>>>(e, vt, mloc, rsum, o2, QKV_ELEMS);
    }

    // 5. out = relu(O Wo^T + bo) -> fp32  (2-MMA pair-A GEMM)
    {
        dim3 grid(DD / BN, M / BM, 1);
        gemm_p3<<<grid, THREADS, P3SMEM>>>(o2, wo16, bo, out, M, DD, HH,
                                           QKV_ELEMS);
    }
}